// round 8
// baseline (speedup 1.0000x reference)
#include <cuda_runtime.h>
#include <cuda_bf16.h>
#include <math.h>
#include <stdint.h>

#define NROWS 8192
#define DIMK  512
#define KTOP  10
#define CAND  32
#define SCALE 0.04419417382415922f   // 512^-0.5

// Scratch (bss): fp32 embeddings (unscaled) + bf16 copies + candidate lists
__device__ float          g_eh[NROWS * DIMK];
__device__ float          g_et[NROWS * DIMK];
__device__ __nv_bfloat16  g_bh[NROWS * DIMK];
__device__ __nv_bfloat16  g_bt[NROWS * DIMK];
__device__ int            g_cand[NROWS * CAND];

// ---------------------------------------------------------------------------
// sm_80-era primitives (base compute_103 target — no tcgen05)
// ---------------------------------------------------------------------------
__device__ __forceinline__ uint32_t smem_to_u32(const void* p) {
    uint32_t a;
    asm("{ .reg .u64 t; cvta.to.shared.u64 t, %1; cvt.u32.u64 %0, t; }" : "=r"(a) : "l"(p));
    return a;
}
__device__ __forceinline__ void ldsm4(uint32_t& r0, uint32_t& r1, uint32_t& r2, uint32_t& r3,
                                      uint32_t addr) {
    asm volatile("ldmatrix.sync.aligned.m8n8.x4.shared.b16 {%0,%1,%2,%3}, [%4];"
                 : "=r"(r0), "=r"(r1), "=r"(r2), "=r"(r3) : "r"(addr));
}
__device__ __forceinline__ void mma16816(float* c, const uint32_t* a, uint32_t b0, uint32_t b1) {
    asm volatile(
        "mma.sync.aligned.m16n8k16.row.col.f32.bf16.bf16.f32 "
        "{%0,%1,%2,%3}, {%4,%5,%6,%7}, {%8,%9}, {%0,%1,%2,%3};"
        : "+f"(c[0]), "+f"(c[1]), "+f"(c[2]), "+f"(c[3])
        : "r"(a[0]), "r"(a[1]), "r"(a[2]), "r"(a[3]), "r"(b0), "r"(b1));
}
#define CP_ASYNC16(dst, src) \
    asm volatile("cp.async.ca.shared.global [%0], [%1], 16;" :: "r"(dst), "l"(src))
#define CP_COMMIT() asm volatile("cp.async.commit_group;" ::: "memory")
#define CP_WAIT(n)  asm volatile("cp.async.wait_group %0;" :: "n"(n) : "memory")
#define SW128(b) ((b) ^ (((b) >> 3) & 0x70))

// ---------------------------------------------------------------------------
// Kernel A: E = X @ W^T + b (UNSCALED), emitted fp32 + bf16
// ---------------------------------------------------------------------------
__global__ void embed_kernel(const float* __restrict__ X,
                             const float* __restrict__ W0, const float* __restrict__ b0,
                             const float* __restrict__ W1, const float* __restrict__ b1)
{
    const int z = blockIdx.z;
    const float* W    = z ? W1 : W0;
    const float* bias = z ? b1 : b0;
    float* of         = z ? g_et : g_eh;
    __nv_bfloat16* ob = z ? g_bt : g_bh;

    __shared__ float Xs[32][64];
    __shared__ float Ws[32][64];

    const int tid = threadIdx.x;
    const int rb = blockIdx.y * 64;
    const int cb = blockIdx.x * 64;
    const int ty = tid >> 5;
    const int tx = tid & 31;

    float acc[8][2];
    #pragma unroll
    for (int i = 0; i < 8; i++) { acc[i][0] = 0.f; acc[i][1] = 0.f; }

    const int lr = tid & 63;
    const int lk = (tid >> 6) * 8;

    for (int kc = 0; kc < DIMK; kc += 32) {
        __syncthreads();
        #pragma unroll
        for (int j = 0; j < 8; j += 4) {
            float4 xv = *(const float4*)(X + (size_t)(rb + lr) * DIMK + kc + lk + j);
            Xs[lk + j + 0][lr] = xv.x; Xs[lk + j + 1][lr] = xv.y;
            Xs[lk + j + 2][lr] = xv.z; Xs[lk + j + 3][lr] = xv.w;
            float4 wv = *(const float4*)(W + (size_t)(cb + lr) * DIMK + kc + lk + j);
            Ws[lk + j + 0][lr] = wv.x; Ws[lk + j + 1][lr] = wv.y;
            Ws[lk + j + 2][lr] = wv.z; Ws[lk + j + 3][lr] = wv.w;
        }
        __syncthreads();
        #pragma unroll
        for (int k = 0; k < 32; k++) {
            float4 a0 = *(const float4*)&Xs[k][ty * 8];
            float4 a1 = *(const float4*)&Xs[k][ty * 8 + 4];
            float2 wb = *(const float2*)&Ws[k][2 * tx];
            float av[8] = {a0.x, a0.y, a0.z, a0.w, a1.x, a1.y, a1.z, a1.w};
            #pragma unroll
            for (int i = 0; i < 8; i++) {
                acc[i][0] = fmaf(av[i], wb.x, acc[i][0]);
                acc[i][1] = fmaf(av[i], wb.y, acc[i][1]);
            }
        }
    }

    const float bv0 = bias[cb + 2 * tx], bv1 = bias[cb + 2 * tx + 1];
    #pragma unroll
    for (int i = 0; i < 8; i++) {
        int row = rb + ty * 8 + i;
        size_t base = (size_t)row * DIMK + cb + 2 * tx;
        float e0 = acc[i][0] + bv0;
        float e1 = acc[i][1] + bv1;
        *(float2*)(of + base) = make_float2(e0, e1);
        __nv_bfloat162 p;
        p.x = __float2bfloat16_rn(e0);
        p.y = __float2bfloat16_rn(e1);
        *(__nv_bfloat162*)(ob + base) = p;
    }
}

// ---------------------------------------------------------------------------
// Kernel B: bf16 HMMA logits (approximate) + per-row top-32 CANDIDATES.
// Grid 128 x 64-row stripes; 256 thr (8 warps, 2x4); A stripe persistent in
// smem; B in 128-col tiles, 64-k chunks double-buffered via cp.async.
// ---------------------------------------------------------------------------
#define MBLK   64
#define NTILE  128
#define KC     64
#define NCHUNK (DIMK / KC)              // 8

#define OFF_A      0                    // 8 sub-tiles x 8192 B = 65536
#define OFF_B      65536                // 2 x 16384 = 32768
#define OFF_STAGE  98304                // 64 x 129 x 4 = 33024
#define STAGE_STRIDE 129
#define OFF_TOPV   131328               // 64 x 32 x 4
#define OFF_TOPI   139520               // 64 x 32 x 4
#define SMEM_LG    147712

__global__ void __launch_bounds__(256, 1)
logits_cand_kernel()
{
    extern __shared__ char smem[];
    const uint32_t smem_base = smem_to_u32(smem);
    const int tid  = threadIdx.x;
    const int wid  = tid >> 5;
    const int lane = tid & 31;
    const int rb   = blockIdx.x * MBLK;

    const int m_base = (wid >> 2) * 32;
    const int n_base = (wid & 3) * 32;

    float* stage = (float*)(smem + OFF_STAGE);
    float* topv  = (float*)(smem + OFF_TOPV);
    int*   topi  = (int*)(smem + OFF_TOPI);

    for (int i = tid; i < MBLK * CAND; i += 256) { topv[i] = -INFINITY; topi[i] = 0; }

    // ldmatrix lane address components (validated in R6/R7 numerics)
    const int mat = lane >> 3, r8 = lane & 7;
    const int aoff_m = ((mat & 1) << 3) + r8;
    const int aoff_k = (mat >> 1) << 4;
    const int boff_n = ((mat >> 1) << 3) + r8;
    const int boff_k = (mat & 1) << 4;

    // A stripe: 64 rows x 512 k bf16 -> 8 sub-tiles (one per 64-k chunk)
    #pragma unroll
    for (int t = 0; t < 16; t++) {           // 4096 16B units / 256 thr
        int idx = tid + t * 256;
        int c = idx >> 9, rem = idx & 511, r = rem >> 3, g = rem & 7;
        const __nv_bfloat16* src = g_bh + (size_t)(rb + r) * DIMK + c * KC + g * 8;
        uint32_t dst = smem_base + OFF_A + c * 8192 + SW128(r * 128 + g * 16);
        CP_ASYNC16(dst, src);
    }

    auto issue_B = [&](int buf, int cbase, int koff) {
        #pragma unroll
        for (int t = 0; t < 4; t++) {        // 1024 16B units / 256 thr
            int rem = tid + t * 256;
            int r = rem >> 3, g = rem & 7;
            const __nv_bfloat16* src = g_bt + (size_t)(cbase + r) * DIMK + koff + g * 8;
            uint32_t dst = smem_base + OFF_B + buf * 16384 + SW128(r * 128 + g * 16);
            CP_ASYNC16(dst, src);
        }
    };

    issue_B(0, 0, 0);
    CP_COMMIT();                              // group: A stripe + first B chunk

    for (int ct = 0; ct < NROWS / NTILE; ct++) {
        const int cbase = ct * NTILE;
        if (ct > 0) { issue_B(0, cbase, 0); CP_COMMIT(); }

        float acc[2][4][4];
        #pragma unroll
        for (int fm = 0; fm < 2; fm++)
            #pragma unroll
            for (int fn = 0; fn < 4; fn++)
                #pragma unroll
                for (int q = 0; q < 4; q++) acc[fm][fn][q] = 0.f;

        for (int kc = 0; kc < NCHUNK; kc++) {
            if (kc < NCHUNK - 1) { issue_B((kc + 1) & 1, cbase, (kc + 1) * KC); CP_COMMIT(); }
            if (kc < NCHUNK - 1) { CP_WAIT(1); } else { CP_WAIT(0); }
            __syncthreads();

            const uint32_t Ab = smem_base + OFF_A + kc * 8192;
            const uint32_t Bb = smem_base + OFF_B + (kc & 1) * 16384;

            #pragma unroll
            for (int k16 = 0; k16 < KC / 16; k16++) {
                const int kbyte = k16 * 32;
                uint32_t Af[2][4];
                #pragma unroll
                for (int fm = 0; fm < 2; fm++)
                    ldsm4(Af[fm][0], Af[fm][1], Af[fm][2], Af[fm][3],
                          Ab + SW128((m_base + fm * 16 + aoff_m) * 128 + kbyte + aoff_k));
                uint32_t Bf[2][4];
                #pragma unroll
                for (int fp = 0; fp < 2; fp++)
                    ldsm4(Bf[fp][0], Bf[fp][1], Bf[fp][2], Bf[fp][3],
                          Bb + SW128((n_base + fp * 16 + boff_n) * 128 + kbyte + boff_k));
                #pragma unroll
                for (int fm = 0; fm < 2; fm++) {
                    mma16816(acc[fm][0], Af[fm], Bf[0][0], Bf[0][1]);
                    mma16816(acc[fm][1], Af[fm], Bf[0][2], Bf[0][3]);
                    mma16816(acc[fm][2], Af[fm], Bf[1][0], Bf[1][1]);
                    mma16816(acc[fm][3], Af[fm], Bf[1][2], Bf[1][3]);
                }
            }
            __syncthreads();
        }

        // stage 64x128 approx logits (stride 129, conflict-free row scans)
        #pragma unroll
        for (int fm = 0; fm < 2; fm++)
            #pragma unroll
            for (int fn = 0; fn < 4; fn++) {
                int row = m_base + fm * 16 + (lane >> 2);
                int col = n_base + fn * 8 + (lane & 3) * 2;
                stage[row * STAGE_STRIDE + col]           = acc[fm][fn][0];
                stage[row * STAGE_STRIDE + col + 1]       = acc[fm][fn][1];
                stage[(row + 8) * STAGE_STRIDE + col]     = acc[fm][fn][2];
                stage[(row + 8) * STAGE_STRIDE + col + 1] = acc[fm][fn][3];
            }
        __syncthreads();

        // one thread per row: maintain top-32 candidate list
        if (tid < MBLK) {
            float* tv = topv + tid * CAND;
            int*   ti = topi + tid * CAND;
            const float* crow = stage + tid * STAGE_STRIDE;
            float kv = tv[CAND - 1];
            for (int c = 0; c < NTILE; c++) {
                float v = crow[c];
                if (v > kv) {
                    int j = CAND - 1;
                    while (j > 0 && v > tv[j - 1]) {
                        tv[j] = tv[j - 1]; ti[j] = ti[j - 1]; j--;
                    }
                    tv[j] = v; ti[j] = cbase + c;
                    kv = tv[CAND - 1];
                }
            }
        }
        __syncthreads();
    }

    // write candidate indices (coalesced)
    for (int j = tid; j < MBLK * CAND; j += 256)
        g_cand[rb * CAND + j] = topi[j];
}

// ---------------------------------------------------------------------------
// Kernel C: exact fp32 rerank of 32 candidates/row + softmax + edge emission.
// Warp per row; lane per candidate; strictly k-sequential fp32 accumulation
// (same rounding class as the R2-passing fp32 kernel), post-scaled like JAX.
// ---------------------------------------------------------------------------
__global__ void __launch_bounds__(256)
rerank_kernel(float* __restrict__ src_p, float* __restrict__ dst_p,
              float* __restrict__ w_p)
{
    __shared__ float eh_s[8][DIMK];
    __shared__ float cv[8][CAND];
    __shared__ int   cix[8][CAND];

    const int tid = threadIdx.x, wid = tid >> 5, lane = tid & 31;
    const int rowblk = blockIdx.x * 8;

    for (int i = tid; i < 8 * (DIMK / 4); i += 256) {
        int r = i >> 7, u = (i & 127) * 4;
        *(float4*)&eh_s[r][u] = *(const float4*)(g_eh + (size_t)(rowblk + r) * DIMK + u);
    }
    __syncthreads();

    const int row  = rowblk + wid;
    const int cand = g_cand[row * CAND + lane];
    const float* bt = g_et + (size_t)cand * DIMK;
    const float* ah = eh_s[wid];

    float acc = 0.f;
    #pragma unroll 8
    for (int k = 0; k < DIMK; k += 4) {
        float4 b = *(const float4*)(bt + k);
        acc = fmaf(ah[k],     b.x, acc);
        acc = fmaf(ah[k + 1], b.y, acc);
        acc = fmaf(ah[k + 2], b.z, acc);
        acc = fmaf(ah[k + 3], b.w, acc);
    }
    cv[wid][lane]  = acc * SCALE;     // post-scale, matching jax (e_h@e_t.T)*scale
    cix[wid][lane] = cand;
    __syncwarp();

    if (lane == 0) {
        float tv[KTOP]; int ti[KTOP];
        #pragma unroll
        for (int j = 0; j < KTOP; j++) { tv[j] = -INFINITY; ti[j] = 0x7FFFFFFF; }
        for (int c = 0; c < CAND; c++) {
            float v = cv[wid][c]; int ix = cix[wid][c];
            // lax.top_k order: value desc, index asc on ties
            if (v > tv[KTOP - 1] || (v == tv[KTOP - 1] && ix < ti[KTOP - 1])) {
                int j = KTOP - 1;
                while (j > 0 && (v > tv[j - 1] || (v == tv[j - 1] && ix < ti[j - 1]))) {
                    tv[j] = tv[j - 1]; ti[j] = ti[j - 1]; j--;
                }
                tv[j] = v; ti[j] = ix;
            }
        }
        float m = tv[0];
        float e[KTOP]; float s = 0.f;
        #pragma unroll
        for (int j = 0; j < KTOP; j++) { e[j] = expf(tv[j] - m); s += e[j]; }
        #pragma unroll
        for (int j = 0; j < KTOP; j++) {
            int o = row * KTOP + j;
            if (src_p) src_p[o] = (float)row;
            if (dst_p) dst_p[o] = (float)ti[j];
            if (w_p)   w_p[o]   = e[j] / s;
        }
    }
}

// ---------------------------------------------------------------------------
extern "C" void kernel_launch(void* const* d_in, const int* in_sizes, int n_in,
                              void* d_out, int out_size)
{
    const float* X  = (const float*)d_in[0];
    const float* Wh = (const float*)d_in[1];
    const float* bh = (const float*)d_in[2];
    const float* Wt = (const float*)d_in[3];
    const float* bt = (const float*)d_in[4];

    cudaFuncSetAttribute(logits_cand_kernel,
                         cudaFuncAttributeMaxDynamicSharedMemorySize, SMEM_LG);

    embed_kernel<<<dim3(DIMK / 64, NROWS / 64, 2), 256>>>(X, Wh, bh, Wt, bt);
    logits_cand_kernel<<<NROWS / MBLK, 256, SMEM_LG>>>();

    const int NK = NROWS * KTOP;   // 81920
    float* out = (float*)d_out;
    float *sp = nullptr, *dp = nullptr, *wp = nullptr;
    if (out_size >= 3 * NK)      { sp = out; dp = out + NK; wp = out + 2 * NK; }
    else if (out_size == 2 * NK) { sp = out; dp = out + NK; }
    else                         { wp = out; }

    rerank_kernel<<<NROWS / 8, 256>>>(sp, dp, wp);
}

// round 12
// speedup vs baseline: 4.1250x; 4.1250x over previous
#include <cuda_runtime.h>
#include <cuda_bf16.h>
#include <math.h>
#include <stdint.h>

#define NROWS 8192
#define DIMK  512
#define KTOP  10
#define CAND  32
#define SCALE 0.04419417382415922f   // 512^-0.5

// Scratch (bss): fp32 embeddings (unscaled) + bf16 copies + candidate lists
__device__ float          g_eh[NROWS * DIMK];
__device__ float          g_et[NROWS * DIMK];
__device__ __nv_bfloat16  g_bh[NROWS * DIMK];
__device__ __nv_bfloat16  g_bt[NROWS * DIMK];
__device__ int            g_cand[NROWS * CAND];

// ---------------------------------------------------------------------------
// sm_80-era primitives (base compute_103 target — no tcgen05)
// ---------------------------------------------------------------------------
__device__ __forceinline__ uint32_t smem_to_u32(const void* p) {
    uint32_t a;
    asm("{ .reg .u64 t; cvta.to.shared.u64 t, %1; cvt.u32.u64 %0, t; }" : "=r"(a) : "l"(p));
    return a;
}
__device__ __forceinline__ void ldsm4(uint32_t& r0, uint32_t& r1, uint32_t& r2, uint32_t& r3,
                                      uint32_t addr) {
    asm volatile("ldmatrix.sync.aligned.m8n8.x4.shared.b16 {%0,%1,%2,%3}, [%4];"
                 : "=r"(r0), "=r"(r1), "=r"(r2), "=r"(r3) : "r"(addr));
}
__device__ __forceinline__ void mma16816(float* c, const uint32_t* a, uint32_t b0, uint32_t b1) {
    asm volatile(
        "mma.sync.aligned.m16n8k16.row.col.f32.bf16.bf16.f32 "
        "{%0,%1,%2,%3}, {%4,%5,%6,%7}, {%8,%9}, {%0,%1,%2,%3};"
        : "+f"(c[0]), "+f"(c[1]), "+f"(c[2]), "+f"(c[3])
        : "r"(a[0]), "r"(a[1]), "r"(a[2]), "r"(a[3]), "r"(b0), "r"(b1));
}
#define CP_ASYNC16(dst, src) \
    asm volatile("cp.async.ca.shared.global [%0], [%1], 16;" :: "r"(dst), "l"(src))
#define CP_COMMIT() asm volatile("cp.async.commit_group;" ::: "memory")
#define CP_WAIT(n)  asm volatile("cp.async.wait_group %0;" :: "n"(n) : "memory")
#define SW128(b) ((b) ^ (((b) >> 3) & 0x70))

// ---------------------------------------------------------------------------
// Kernel A: E = X @ W^T + b (UNSCALED), emitted fp32 + bf16  (R7-proven)
// ---------------------------------------------------------------------------
__global__ void embed_kernel(const float* __restrict__ X,
                             const float* __restrict__ W0, const float* __restrict__ b0,
                             const float* __restrict__ W1, const float* __restrict__ b1)
{
    const int z = blockIdx.z;
    const float* W    = z ? W1 : W0;
    const float* bias = z ? b1 : b0;
    float* of         = z ? g_et : g_eh;
    __nv_bfloat16* ob = z ? g_bt : g_bh;

    __shared__ float Xs[32][64];
    __shared__ float Ws[32][64];

    const int tid = threadIdx.x;
    const int rb = blockIdx.y * 64;
    const int cb = blockIdx.x * 64;
    const int ty = tid >> 5;
    const int tx = tid & 31;

    float acc[8][2];
    #pragma unroll
    for (int i = 0; i < 8; i++) { acc[i][0] = 0.f; acc[i][1] = 0.f; }

    const int lr = tid & 63;
    const int lk = (tid >> 6) * 8;

    for (int kc = 0; kc < DIMK; kc += 32) {
        __syncthreads();
        #pragma unroll
        for (int j = 0; j < 8; j += 4) {
            float4 xv = *(const float4*)(X + (size_t)(rb + lr) * DIMK + kc + lk + j);
            Xs[lk + j + 0][lr] = xv.x; Xs[lk + j + 1][lr] = xv.y;
            Xs[lk + j + 2][lr] = xv.z; Xs[lk + j + 3][lr] = xv.w;
            float4 wv = *(const float4*)(W + (size_t)(cb + lr) * DIMK + kc + lk + j);
            Ws[lk + j + 0][lr] = wv.x; Ws[lk + j + 1][lr] = wv.y;
            Ws[lk + j + 2][lr] = wv.z; Ws[lk + j + 3][lr] = wv.w;
        }
        __syncthreads();
        #pragma unroll
        for (int k = 0; k < 32; k++) {
            float4 a0 = *(const float4*)&Xs[k][ty * 8];
            float4 a1 = *(const float4*)&Xs[k][ty * 8 + 4];
            float2 wb = *(const float2*)&Ws[k][2 * tx];
            float av[8] = {a0.x, a0.y, a0.z, a0.w, a1.x, a1.y, a1.z, a1.w};
            #pragma unroll
            for (int i = 0; i < 8; i++) {
                acc[i][0] = fmaf(av[i], wb.x, acc[i][0]);
                acc[i][1] = fmaf(av[i], wb.y, acc[i][1]);
            }
        }
    }

    const float bv0 = bias[cb + 2 * tx], bv1 = bias[cb + 2 * tx + 1];
    #pragma unroll
    for (int i = 0; i < 8; i++) {
        int row = rb + ty * 8 + i;
        size_t base = (size_t)row * DIMK + cb + 2 * tx;
        float e0 = acc[i][0] + bv0;
        float e1 = acc[i][1] + bv1;
        *(float2*)(of + base) = make_float2(e0, e1);
        __nv_bfloat162 p;
        p.x = __float2bfloat16_rn(e0);
        p.y = __float2bfloat16_rn(e1);
        *(__nv_bfloat162*)(ob + base) = p;
    }
}

// ---------------------------------------------------------------------------
// Kernel B: bf16 HMMA approx logits + warp-parallel register top-32 select.
// 512 threads (16 warps, 2x8), 64-row stripe/block, N-tiles of 128,
// 64-k chunks, 4-buffer depth-2 cp.async pipeline across tile boundaries.
// ---------------------------------------------------------------------------
#define MBLK   64
#define NTILE  128
#define KC     64
#define NCHUNK (DIMK / KC)              // 8
#define GTOT   ((NROWS / NTILE) * NCHUNK)   // 512 global chunks

#define OFF_A      0                    // 8 sub-tiles x 8192 B = 65536
#define OFF_B      65536                // 4 x 16384 = 65536
#define OFF_STAGE  131072               // 64 x 129 x 4 = 33024
#define STAGE_STRIDE 129
#define SMEM_LG    164096

__global__ void __launch_bounds__(512, 1)
logits_cand_kernel()
{
    extern __shared__ char smem[];
    const uint32_t smem_base = smem_to_u32(smem);
    const int tid  = threadIdx.x;
    const int wid  = tid >> 5;
    const int lane = tid & 31;
    const int rb   = blockIdx.x * MBLK;

    const int m_base = (wid >> 3) * 32;   // 0/32
    const int n_base = (wid & 7) * 16;    // 0..112

    float* stage = (float*)(smem + OFF_STAGE);

    // register-resident sorted top-32 lists: warp owns rows 4*wid..4*wid+3,
    // lane l holds slot l of each row's list (sorted desc, ties idx asc)
    float lv[4]; int li[4];
    #pragma unroll
    for (int q = 0; q < 4; q++) { lv[q] = -INFINITY; li[q] = 0; }

    // ldmatrix lane address components (numerics validated in R7)
    const int mat = lane >> 3, r8 = lane & 7;
    const int aoff_m = ((mat & 1) << 3) + r8;
    const int aoff_k = (mat >> 1) << 4;
    const int boff_n = ((mat >> 1) << 3) + r8;
    const int boff_k = (mat & 1) << 4;

    // A stripe: 64 rows x 512 k bf16 -> 8 sub-tiles (4096 16B units, 8/thread)
    #pragma unroll
    for (int t = 0; t < 8; t++) {
        int idx = tid + t * 512;
        int c = idx >> 9, rem = idx & 511, r = rem >> 3, g = rem & 7;
        const __nv_bfloat16* src = g_bh + (size_t)(rb + r) * DIMK + c * KC + g * 8;
        uint32_t dst = smem_base + OFF_A + c * 8192 + SW128(r * 128 + g * 16);
        CP_ASYNC16(dst, src);
    }

    auto issue_B = [&](int g) {
        const int cbase = (g >> 3) * NTILE;
        const int koff  = (g & 7) * KC;
        const int buf   = g & 3;
        #pragma unroll
        for (int t = 0; t < 2; t++) {     // 1024 16B units / 512 thr
            int rem = tid + t * 512;
            int r = rem >> 3, gg = rem & 7;
            const __nv_bfloat16* src = g_bt + (size_t)(cbase + r) * DIMK + koff + gg * 8;
            uint32_t dst = smem_base + OFF_B + buf * 16384 + SW128(r * 128 + gg * 16);
            CP_ASYNC16(dst, src);
        }
    };

    issue_B(0); CP_COMMIT();              // group 0: A stripe + B chunk 0
    issue_B(1); CP_COMMIT();              // group 1

    float acc[2][2][4];

    for (int ct = 0; ct < NROWS / NTILE; ct++) {
        const int cbase = ct * NTILE;

        #pragma unroll
        for (int fm = 0; fm < 2; fm++)
            #pragma unroll
            for (int fn = 0; fn < 2; fn++)
                #pragma unroll
                for (int q = 0; q < 4; q++) acc[fm][fn][q] = 0.f;

        for (int kc = 0; kc < NCHUNK; kc++) {
            const int g = ct * NCHUNK + kc;
            if (g + 2 < GTOT) { issue_B(g + 2); CP_COMMIT(); }
            if (g < GTOT - 2)      { CP_WAIT(2); }
            else if (g == GTOT - 2){ CP_WAIT(1); }
            else                   { CP_WAIT(0); }
            __syncthreads();

            const uint32_t Ab = smem_base + OFF_A + kc * 8192;
            const uint32_t Bb = smem_base + OFF_B + (g & 3) * 16384;

            #pragma unroll
            for (int k16 = 0; k16 < KC / 16; k16++) {
                const int kbyte = k16 * 32;
                uint32_t Af[2][4];
                #pragma unroll
                for (int fm = 0; fm < 2; fm++)
                    ldsm4(Af[fm][0], Af[fm][1], Af[fm][2], Af[fm][3],
                          Ab + SW128((m_base + fm * 16 + aoff_m) * 128 + kbyte + aoff_k));
                uint32_t Bf[4];
                ldsm4(Bf[0], Bf[1], Bf[2], Bf[3],
                      Bb + SW128((n_base + boff_n) * 128 + kbyte + boff_k));
                #pragma unroll
                for (int fm = 0; fm < 2; fm++) {
                    mma16816(acc[fm][0], Af[fm], Bf[0], Bf[1]);
                    mma16816(acc[fm][1], Af[fm], Bf[2], Bf[3]);
                }
            }
            __syncthreads();
        }

        // stage 64x128 approx logits (stride 129)
        #pragma unroll
        for (int fm = 0; fm < 2; fm++)
            #pragma unroll
            for (int fn = 0; fn < 2; fn++) {
                int row = m_base + fm * 16 + (lane >> 2);
                int col = n_base + fn * 8 + (lane & 3) * 2;
                stage[row * STAGE_STRIDE + col]           = acc[fm][fn][0];
                stage[row * STAGE_STRIDE + col + 1]       = acc[fm][fn][1];
                stage[(row + 8) * STAGE_STRIDE + col]     = acc[fm][fn][2];
                stage[(row + 8) * STAGE_STRIDE + col + 1] = acc[fm][fn][3];
            }
        __syncthreads();

        // warp-parallel select: warp handles rows 4*wid..4*wid+3
        #pragma unroll
        for (int q = 0; q < 4; q++) {
            const int row = wid * 4 + q;
            const float* crow = stage + row * STAGE_STRIDE;
            float kv = __shfl_sync(0xffffffffu, lv[q], 31);
            #pragma unroll
            for (int j = 0; j < 4; j++) {
                float v = crow[32 * j + lane];
                unsigned m = __ballot_sync(0xffffffffu, v > kv);
                while (m) {
                    int b = __ffs(m) - 1; m &= m - 1;
                    float vb = __shfl_sync(0xffffffffu, v, b);
                    int   cb = cbase + 32 * j + b;
                    unsigned gt = __ballot_sync(0xffffffffu,
                        (lv[q] > vb) || (lv[q] == vb && li[q] < cb));
                    int p = __popc(gt);
                    if (p < CAND) {
                        float pv = __shfl_up_sync(0xffffffffu, lv[q], 1);
                        int   pi = __shfl_up_sync(0xffffffffu, li[q], 1);
                        if (lane > p)  { lv[q] = pv; li[q] = pi; }
                        if (lane == p) { lv[q] = vb; li[q] = cb; }
                        kv = __shfl_sync(0xffffffffu, lv[q], 31);
                    }
                }
            }
        }
        // no extra sync needed: next stage write is separated by the
        // per-chunk __syncthreads of the following tile's mainloop
    }

    // write candidates: lane l writes slot l (coalesced)
    #pragma unroll
    for (int q = 0; q < 4; q++)
        g_cand[(size_t)(rb + wid * 4 + q) * CAND + lane] = li[q];
}

// ---------------------------------------------------------------------------
// Kernel C: exact fp32 rerank (R7-proven) + softmax + edge emission.
// ---------------------------------------------------------------------------
__global__ void __launch_bounds__(256)
rerank_kernel(float* __restrict__ src_p, float* __restrict__ dst_p,
              float* __restrict__ w_p)
{
    __shared__ float eh_s[8][DIMK];
    __shared__ float cv[8][CAND];
    __shared__ int   cix[8][CAND];

    const int tid = threadIdx.x, wid = tid >> 5, lane = tid & 31;
    const int rowblk = blockIdx.x * 8;

    for (int i = tid; i < 8 * (DIMK / 4); i += 256) {
        int r = i >> 7, u = (i & 127) * 4;
        *(float4*)&eh_s[r][u] = *(const float4*)(g_eh + (size_t)(rowblk + r) * DIMK + u);
    }
    __syncthreads();

    const int row  = rowblk + wid;
    const int cand = g_cand[(size_t)row * CAND + lane];
    const float* bt = g_et + (size_t)cand * DIMK;
    const float* ah = eh_s[wid];

    float acc = 0.f;
    #pragma unroll 8
    for (int k = 0; k < DIMK; k += 4) {
        float4 b = *(const float4*)(bt + k);
        acc = fmaf(ah[k],     b.x, acc);
        acc = fmaf(ah[k + 1], b.y, acc);
        acc = fmaf(ah[k + 2], b.z, acc);
        acc = fmaf(ah[k + 3], b.w, acc);
    }
    cv[wid][lane]  = acc * SCALE;     // post-scale, matching jax (e_h@e_t.T)*scale
    cix[wid][lane] = cand;
    __syncwarp();

    if (lane == 0) {
        float tv[KTOP]; int ti[KTOP];
        #pragma unroll
        for (int j = 0; j < KTOP; j++) { tv[j] = -INFINITY; ti[j] = 0x7FFFFFFF; }
        for (int c = 0; c < CAND; c++) {
            float v = cv[wid][c]; int ix = cix[wid][c];
            if (v > tv[KTOP - 1] || (v == tv[KTOP - 1] && ix < ti[KTOP - 1])) {
                int j = KTOP - 1;
                while (j > 0 && (v > tv[j - 1] || (v == tv[j - 1] && ix < ti[j - 1]))) {
                    tv[j] = tv[j - 1]; ti[j] = ti[j - 1]; j--;
                }
                tv[j] = v; ti[j] = ix;
            }
        }
        float m = tv[0];
        float e[KTOP]; float s = 0.f;
        #pragma unroll
        for (int j = 0; j < KTOP; j++) { e[j] = expf(tv[j] - m); s += e[j]; }
        #pragma unroll
        for (int j = 0; j < KTOP; j++) {
            int o = row * KTOP + j;
            if (src_p) src_p[o] = (float)row;
            if (dst_p) dst_p[o] = (float)ti[j];
            if (w_p)   w_p[o]   = e[j] / s;
        }
    }
}

// ---------------------------------------------------------------------------
extern "C" void kernel_launch(void* const* d_in, const int* in_sizes, int n_in,
                              void* d_out, int out_size)
{
    const float* X  = (const float*)d_in[0];
    const float* Wh = (const float*)d_in[1];
    const float* bh = (const float*)d_in[2];
    const float* Wt = (const float*)d_in[3];
    const float* bt = (const float*)d_in[4];

    cudaFuncSetAttribute(logits_cand_kernel,
                         cudaFuncAttributeMaxDynamicSharedMemorySize, SMEM_LG);

    embed_kernel<<<dim3(DIMK / 64, NROWS / 64, 2), 256>>>(X, Wh, bh, Wt, bt);
    logits_cand_kernel<<<NROWS / MBLK, 512, SMEM_LG>>>();

    const int NK = NROWS * KTOP;   // 81920
    float* out = (float*)d_out;
    float *sp = nullptr, *dp = nullptr, *wp = nullptr;
    if (out_size >= 3 * NK)      { sp = out; dp = out + NK; wp = out + 2 * NK; }
    else if (out_size == 2 * NK) { sp = out; dp = out + NK; }
    else                         { wp = out; }

    rerank_kernel<<<NROWS / 8, 256>>>(sp, dp, wp);
}

// round 13
// speedup vs baseline: 5.4099x; 1.3115x over previous
#include <cuda_runtime.h>
#include <cuda_bf16.h>
#include <math.h>
#include <stdint.h>

#define NROWS 8192
#define DIMK  512
#define KTOP  10
#define CAND  32
#define SCALE 0.04419417382415922f   // 512^-0.5

// Scratch (bss): fp32 embeddings (unscaled) + bf16 copies + candidate lists
__device__ float          g_eh[NROWS * DIMK];
__device__ float          g_et[NROWS * DIMK];
__device__ __nv_bfloat16  g_bh[NROWS * DIMK];
__device__ __nv_bfloat16  g_bt[NROWS * DIMK];
__device__ int            g_cand[NROWS * CAND];

// ---------------------------------------------------------------------------
// sm_80-era primitives (base compute_103 target — no tcgen05)
// ---------------------------------------------------------------------------
__device__ __forceinline__ uint32_t smem_to_u32(const void* p) {
    uint32_t a;
    asm("{ .reg .u64 t; cvta.to.shared.u64 t, %1; cvt.u32.u64 %0, t; }" : "=r"(a) : "l"(p));
    return a;
}
__device__ __forceinline__ void ldsm4(uint32_t& r0, uint32_t& r1, uint32_t& r2, uint32_t& r3,
                                      uint32_t addr) {
    asm volatile("ldmatrix.sync.aligned.m8n8.x4.shared.b16 {%0,%1,%2,%3}, [%4];"
                 : "=r"(r0), "=r"(r1), "=r"(r2), "=r"(r3) : "r"(addr));
}
__device__ __forceinline__ void mma16816(float* c, const uint32_t* a, uint32_t b0, uint32_t b1) {
    asm volatile(
        "mma.sync.aligned.m16n8k16.row.col.f32.bf16.bf16.f32 "
        "{%0,%1,%2,%3}, {%4,%5,%6,%7}, {%8,%9}, {%0,%1,%2,%3};"
        : "+f"(c[0]), "+f"(c[1]), "+f"(c[2]), "+f"(c[3])
        : "r"(a[0]), "r"(a[1]), "r"(a[2]), "r"(a[3]), "r"(b0), "r"(b1));
}
#define CP_ASYNC16(dst, src) \
    asm volatile("cp.async.ca.shared.global [%0], [%1], 16;" :: "r"(dst), "l"(src))
#define CP_COMMIT() asm volatile("cp.async.commit_group;" ::: "memory")
#define CP_WAIT(n)  asm volatile("cp.async.wait_group %0;" :: "n"(n) : "memory")
#define SW128(b) ((b) ^ (((b) >> 3) & 0x70))

// ---------------------------------------------------------------------------
// Kernel A: E = X @ W^T + b (UNSCALED), fp32 + bf16 out.
// Tile 64 rows x 128 cols, 256 thr, 8x4 micro-tile: 32 FMA per 3 LDS.128
// (halves L1 wavefronts/FMA vs the 8x2 version measured at fma=33%).
// ---------------------------------------------------------------------------
__global__ void embed_kernel(const float* __restrict__ X,
                             const float* __restrict__ W0, const float* __restrict__ b0,
                             const float* __restrict__ W1, const float* __restrict__ b1)
{
    const int z = blockIdx.z;
    const float* W    = z ? W1 : W0;
    const float* bias = z ? b1 : b0;
    float* of         = z ? g_et : g_eh;
    __nv_bfloat16* ob = z ? g_bt : g_bh;

    __shared__ float Xs[32][64];
    __shared__ float Ws[32][128];

    const int tid = threadIdx.x;
    const int rb = blockIdx.y * 64;
    const int cb = blockIdx.x * 128;
    const int ty = tid >> 5;       // 0..7  -> rows ty*8..ty*8+7
    const int tx = tid & 31;       // cols tx*4..tx*4+3

    float acc[8][4];
    #pragma unroll
    for (int i = 0; i < 8; i++)
        #pragma unroll
        for (int j = 0; j < 4; j++) acc[i][j] = 0.f;

    const int lr  = tid & 63;            // X row within tile
    const int lk  = (tid >> 6) * 8;      // X k group (8 k)
    const int lrw = tid & 127;           // W row (= out col) within tile
    const int lkw = (tid >> 7) * 16;     // W k group (16 k)

    for (int kc = 0; kc < DIMK; kc += 32) {
        __syncthreads();
        #pragma unroll
        for (int j = 0; j < 8; j += 4) {
            float4 xv = *(const float4*)(X + (size_t)(rb + lr) * DIMK + kc + lk + j);
            Xs[lk + j + 0][lr] = xv.x; Xs[lk + j + 1][lr] = xv.y;
            Xs[lk + j + 2][lr] = xv.z; Xs[lk + j + 3][lr] = xv.w;
        }
        #pragma unroll
        for (int j = 0; j < 16; j += 4) {
            float4 wv = *(const float4*)(W + (size_t)(cb + lrw) * DIMK + kc + lkw + j);
            Ws[lkw + j + 0][lrw] = wv.x; Ws[lkw + j + 1][lrw] = wv.y;
            Ws[lkw + j + 2][lrw] = wv.z; Ws[lkw + j + 3][lrw] = wv.w;
        }
        __syncthreads();
        #pragma unroll
        for (int k = 0; k < 32; k++) {
            float4 a0 = *(const float4*)&Xs[k][ty * 8];
            float4 a1 = *(const float4*)&Xs[k][ty * 8 + 4];
            float4 b  = *(const float4*)&Ws[k][tx * 4];
            float av[8] = {a0.x, a0.y, a0.z, a0.w, a1.x, a1.y, a1.z, a1.w};
            float bv[4] = {b.x, b.y, b.z, b.w};
            #pragma unroll
            for (int i = 0; i < 8; i++)
                #pragma unroll
                for (int j = 0; j < 4; j++)
                    acc[i][j] = fmaf(av[i], bv[j], acc[i][j]);
        }
    }

    float bv[4];
    #pragma unroll
    for (int j = 0; j < 4; j++) bv[j] = bias[cb + tx * 4 + j];
    #pragma unroll
    for (int i = 0; i < 8; i++) {
        int row = rb + ty * 8 + i;
        size_t base = (size_t)row * DIMK + cb + tx * 4;
        float e[4];
        #pragma unroll
        for (int j = 0; j < 4; j++) e[j] = acc[i][j] + bv[j];
        *(float4*)(of + base) = make_float4(e[0], e[1], e[2], e[3]);
        __nv_bfloat162 p0, p1;
        p0.x = __float2bfloat16_rn(e[0]); p0.y = __float2bfloat16_rn(e[1]);
        p1.x = __float2bfloat16_rn(e[2]); p1.y = __float2bfloat16_rn(e[3]);
        *(__nv_bfloat162*)(ob + base)     = p0;
        *(__nv_bfloat162*)(ob + base + 2) = p1;
    }
}

// ---------------------------------------------------------------------------
// Kernel B: bf16 HMMA approx logits + warp-parallel register top-32 select.
// 512 thr (16 warps, 2x8 grid of 32x32 warp tiles), 64-row stripe/block,
// N-tiles of 256, 64-k chunks, 2x32KB B double buffer (trailing-barrier safe).
// ---------------------------------------------------------------------------
#define MBLK   64
#define NTILE  256
#define KC     64
#define NCHUNK (DIMK / KC)                  // 8
#define GTOT   ((NROWS / NTILE) * NCHUNK)   // 256 global chunks

#define OFF_A      0                        // 8 sub-tiles x 8192 B = 65536
#define OFF_B      65536                    // 2 x 32768 = 65536
#define OFF_STAGE  131072                   // 64 x 260 x 4 = 66560
#define STAGE_STRIDE 260
#define SMEM_LG    197632

__global__ void __launch_bounds__(512, 1)
logits_cand_kernel()
{
    extern __shared__ char smem[];
    const uint32_t smem_base = smem_to_u32(smem);
    const int tid  = threadIdx.x;
    const int wid  = tid >> 5;
    const int lane = tid & 31;
    const int rb   = blockIdx.x * MBLK;

    const int m_base = (wid >> 3) * 32;   // 0/32
    const int n_base = (wid & 7) * 32;    // 0..224

    float* stage = (float*)(smem + OFF_STAGE);

    // register-resident sorted top-32: warp owns rows 4*wid..4*wid+3,
    // lane l holds slot l (sorted desc, ties idx asc)
    float lv[4]; int li[4];
    #pragma unroll
    for (int q = 0; q < 4; q++) { lv[q] = -INFINITY; li[q] = 0; }

    const int mat = lane >> 3, r8 = lane & 7;
    const int aoff_m = ((mat & 1) << 3) + r8;
    const int aoff_k = (mat >> 1) << 4;
    const int boff_n = ((mat >> 1) << 3) + r8;
    const int boff_k = (mat & 1) << 4;

    // A stripe: 64 rows x 512 k bf16 -> 8 sub-tiles (4096 16B units, 8/thread)
    #pragma unroll
    for (int t = 0; t < 8; t++) {
        int idx = tid + t * 512;
        int c = idx >> 9, rem = idx & 511, r = rem >> 3, g = rem & 7;
        const __nv_bfloat16* src = g_bh + (size_t)(rb + r) * DIMK + c * KC + g * 8;
        uint32_t dst = smem_base + OFF_A + c * 8192 + SW128(r * 128 + g * 16);
        CP_ASYNC16(dst, src);
    }

    auto issue_B = [&](int g) {
        const int cbase = (g >> 3) * NTILE;
        const int koff  = (g & 7) * KC;
        const int buf   = g & 1;
        #pragma unroll
        for (int t = 0; t < 4; t++) {     // 2048 16B units / 512 thr
            int rem = tid + t * 512;
            int r = rem >> 3, gg = rem & 7;
            const __nv_bfloat16* src = g_bt + (size_t)(cbase + r) * DIMK + koff + gg * 8;
            uint32_t dst = smem_base + OFF_B + buf * 32768 + SW128(r * 128 + gg * 16);
            CP_ASYNC16(dst, src);
        }
    };

    issue_B(0); CP_COMMIT();              // group 0: A stripe + B chunk 0

    float acc[2][4][4];

    for (int ct = 0; ct < NROWS / NTILE; ct++) {
        const int cbase = ct * NTILE;

        #pragma unroll
        for (int fm = 0; fm < 2; fm++)
            #pragma unroll
            for (int fn = 0; fn < 4; fn++)
                #pragma unroll
                for (int q = 0; q < 4; q++) acc[fm][fn][q] = 0.f;

        for (int kc = 0; kc < NCHUNK; kc++) {
            const int g = ct * NCHUNK + kc;
            // safe w/ 2 buffers: buffer (g+1)&1 was fully read before the
            // trailing barrier of chunk g-1
            if (g + 1 < GTOT) { issue_B(g + 1); CP_COMMIT(); CP_WAIT(1); }
            else              { CP_WAIT(0); }
            __syncthreads();

            const uint32_t Ab = smem_base + OFF_A + kc * 8192;
            const uint32_t Bb = smem_base + OFF_B + (g & 1) * 32768;

            #pragma unroll
            for (int k16 = 0; k16 < KC / 16; k16++) {
                const int kbyte = k16 * 32;
                uint32_t Af[2][4];
                #pragma unroll
                for (int fm = 0; fm < 2; fm++)
                    ldsm4(Af[fm][0], Af[fm][1], Af[fm][2], Af[fm][3],
                          Ab + SW128((m_base + fm * 16 + aoff_m) * 128 + kbyte + aoff_k));
                uint32_t Bf[2][4];
                #pragma unroll
                for (int fp = 0; fp < 2; fp++)
                    ldsm4(Bf[fp][0], Bf[fp][1], Bf[fp][2], Bf[fp][3],
                          Bb + SW128((n_base + fp * 16 + boff_n) * 128 + kbyte + boff_k));
                #pragma unroll
                for (int fm = 0; fm < 2; fm++) {
                    mma16816(acc[fm][0], Af[fm], Bf[0][0], Bf[0][1]);
                    mma16816(acc[fm][1], Af[fm], Bf[0][2], Bf[0][3]);
                    mma16816(acc[fm][2], Af[fm], Bf[1][0], Bf[1][1]);
                    mma16816(acc[fm][3], Af[fm], Bf[1][2], Bf[1][3]);
                }
            }
            __syncthreads();   // trailing barrier: all reads of buf (g&1) done
        }

        // stage 64x256 approx logits (stride 260)
        #pragma unroll
        for (int fm = 0; fm < 2; fm++)
            #pragma unroll
            for (int fn = 0; fn < 4; fn++) {
                int row = m_base + fm * 16 + (lane >> 2);
                int col = n_base + fn * 8 + (lane & 3) * 2;
                *(float2*)(stage + row * STAGE_STRIDE + col) =
                    make_float2(acc[fm][fn][0], acc[fm][fn][1]);
                *(float2*)(stage + (row + 8) * STAGE_STRIDE + col) =
                    make_float2(acc[fm][fn][2], acc[fm][fn][3]);
            }
        __syncthreads();

        // warp-parallel select: warp handles rows 4*wid..4*wid+3
        #pragma unroll
        for (int q = 0; q < 4; q++) {
            const int row = wid * 4 + q;
            const float* crow = stage + row * STAGE_STRIDE;
            float kv = __shfl_sync(0xffffffffu, lv[q], 31);
            #pragma unroll
            for (int j = 0; j < 8; j++) {
                float v = crow[32 * j + lane];
                unsigned m = __ballot_sync(0xffffffffu, v > kv);
                while (m) {
                    int b = __ffs(m) - 1; m &= m - 1;
                    float vb = __shfl_sync(0xffffffffu, v, b);
                    int   cb = cbase + 32 * j + b;
                    unsigned gt = __ballot_sync(0xffffffffu,
                        (lv[q] > vb) || (lv[q] == vb && li[q] < cb));
                    int p = __popc(gt);
                    if (p < CAND) {
                        float pv = __shfl_up_sync(0xffffffffu, lv[q], 1);
                        int   pi = __shfl_up_sync(0xffffffffu, li[q], 1);
                        if (lane > p)  { lv[q] = pv; li[q] = pi; }
                        if (lane == p) { lv[q] = vb; li[q] = cb; }
                        kv = __shfl_sync(0xffffffffu, lv[q], 31);
                    }
                }
            }
        }
        // stage rewrite is 16 barriers away (next tile's mainloop) — safe
    }

    #pragma unroll
    for (int q = 0; q < 4; q++)
        g_cand[(size_t)(rb + wid * 4 + q) * CAND + lane] = li[q];
}

// ---------------------------------------------------------------------------
// Kernel C: exact fp32 rerank, warp-per-row COOPERATIVE (coalesced) dots.
// Lanes split k (16 floats each), shfl-tree reduce; lane0 does top-10 +
// softmax + edge emission (lax.top_k tie semantics).
// ---------------------------------------------------------------------------
__global__ void __launch_bounds__(256)
rerank_kernel(float* __restrict__ src_p, float* __restrict__ dst_p,
              float* __restrict__ w_p)
{
    __shared__ float eh_s[8][DIMK];
    __shared__ float cv[8][CAND];
    __shared__ int   cix[8][CAND];

    const int tid = threadIdx.x, wid = tid >> 5, lane = tid & 31;
    const int rowblk = blockIdx.x * 8;

    for (int i = tid; i < 8 * (DIMK / 4); i += 256) {
        int r = i >> 7, u = (i & 127) * 4;
        *(float4*)&eh_s[r][u] = *(const float4*)(g_eh + (size_t)(rowblk + r) * DIMK + u);
    }
    __syncthreads();

    const int row = rowblk + wid;
    const int* my_cand = g_cand + (size_t)row * CAND;
    const float4* ah = (const float4*)eh_s[wid];

    for (int c = 0; c < CAND; c++) {
        int cand = my_cand[c];                       // warp-broadcast load
        const float4* bt = (const float4*)(g_et + (size_t)cand * DIMK);
        float acc = 0.f;
        #pragma unroll
        for (int j = 0; j < 4; j++) {
            float4 b = bt[j * 32 + lane];            // coalesced: 512B/warp
            float4 a = ah[j * 32 + lane];
            acc = fmaf(a.x, b.x, acc);
            acc = fmaf(a.y, b.y, acc);
            acc = fmaf(a.z, b.z, acc);
            acc = fmaf(a.w, b.w, acc);
        }
        #pragma unroll
        for (int off = 16; off > 0; off >>= 1)
            acc += __shfl_down_sync(0xffffffffu, acc, off);
        if (lane == 0) { cv[wid][c] = acc * SCALE; cix[wid][c] = cand; }
    }
    __syncwarp();

    if (lane == 0) {
        float tv[KTOP]; int ti[KTOP];
        #pragma unroll
        for (int j = 0; j < KTOP; j++) { tv[j] = -INFINITY; ti[j] = 0x7FFFFFFF; }
        for (int c = 0; c < CAND; c++) {
            float v = cv[wid][c]; int ix = cix[wid][c];
            if (v > tv[KTOP - 1] || (v == tv[KTOP - 1] && ix < ti[KTOP - 1])) {
                int j = KTOP - 1;
                while (j > 0 && (v > tv[j - 1] || (v == tv[j - 1] && ix < ti[j - 1]))) {
                    tv[j] = tv[j - 1]; ti[j] = ti[j - 1]; j--;
                }
                tv[j] = v; ti[j] = ix;
            }
        }
        float m = tv[0];
        float e[KTOP]; float s = 0.f;
        #pragma unroll
        for (int j = 0; j < KTOP; j++) { e[j] = expf(tv[j] - m); s += e[j]; }
        #pragma unroll
        for (int j = 0; j < KTOP; j++) {
            int o = row * KTOP + j;
            if (src_p) src_p[o] = (float)row;
            if (dst_p) dst_p[o] = (float)ti[j];
            if (w_p)   w_p[o]   = e[j] / s;
        }
    }
}

// ---------------------------------------------------------------------------
extern "C" void kernel_launch(void* const* d_in, const int* in_sizes, int n_in,
                              void* d_out, int out_size)
{
    const float* X  = (const float*)d_in[0];
    const float* Wh = (const float*)d_in[1];
    const float* bh = (const float*)d_in[2];
    const float* Wt = (const float*)d_in[3];
    const float* bt = (const float*)d_in[4];

    cudaFuncSetAttribute(logits_cand_kernel,
                         cudaFuncAttributeMaxDynamicSharedMemorySize, SMEM_LG);

    embed_kernel<<<dim3(DIMK / 128, NROWS / 64, 2), 256>>>(X, Wh, bh, Wt, bt);
    logits_cand_kernel<<<NROWS / MBLK, 512, SMEM_LG>>>();

    const int NK = NROWS * KTOP;   // 81920
    float* out = (float*)d_out;
    float *sp = nullptr, *dp = nullptr, *wp = nullptr;
    if (out_size >= 3 * NK)      { sp = out; dp = out + NK; wp = out + 2 * NK; }
    else if (out_size == 2 * NK) { sp = out; dp = out + NK; }
    else                         { wp = out; }

    rerank_kernel<<<NROWS / 8, 256>>>(sp, dp, wp);
}